// round 4
// baseline (speedup 1.0000x reference)
#include <cuda_runtime.h>
#include <cuda_bf16.h>

typedef unsigned long long u64;
__device__ __forceinline__ u64 pk2(float lo, float hi) {
    u64 r; asm("mov.b64 %0, {%1, %2};" : "=l"(r) : "f"(lo), "f"(hi)); return r;
}
__device__ __forceinline__ void unpk2(u64 v, float& lo, float& hi) {
    asm("mov.b64 {%0, %1}, %2;" : "=f"(lo), "=f"(hi) : "l"(v));
}
__device__ __forceinline__ u64 mul2(u64 a, u64 b) {
    u64 r; asm("mul.rn.f32x2 %0, %1, %2;" : "=l"(r) : "l"(a), "l"(b)); return r;
}
__device__ __forceinline__ u64 fma2(u64 a, u64 b, u64 c) {
    u64 r; asm("fma.rn.f32x2 %0, %1, %2, %3;" : "=l"(r) : "l"(a), "l"(b), "l"(c)); return r;
}

#define PAIRS 2   // 4 samples per thread

// Single fused kernel. Each block redundantly computes the 100 bilinear-form
// coefficients (shuffle-based 16x16 unitary sim, ~1.5K cycles), then processes
// its slice of the batch with packed f32x2 math. Register-lean: sincos table
// and coefficients live in shared, monomial bases capped at 2 pairs.
__global__ void __launch_bounds__(256, 3)
qnn_fused(const float4* __restrict__ x, float4* __restrict__ out,
          const float* __restrict__ w, int npair)
{
    __shared__ float2 wcs[36];       // (cos, sin) of half-angles
    __shared__ float2 S[16][16];     // S[col][k] = U[k][col]
    __shared__ float  coefS[100];
    __shared__ u64    scp[100];
    const int tid = threadIdx.x;

    if (tid < 36) {
        float s, c; __sincosf(0.5f * w[tid], &s, &c);
        wcs[tid] = make_float2(c, s);
    }
    if (tid >= 64 && tid < 164) coefS[tid - 64] = 0.f;
    __syncthreads();

    // ---------- per-block setup: simulate the 16x16 variational unitary ----------
    {
        const int col = tid >> 4, k = tid & 15;  // 16-lane group = one column
        float ar = (k == col) ? 1.f : 0.f, ai = 0.f;

        // CNOT-ring inverse permutation (src index for this lane)
        int sidx = k;
        if (sidx & 1) sidx ^= 8;
        if (sidx & 2) sidx ^= 1;
        if (sidx & 4) sidx ^= 2;
        if (sidx & 8) sidx ^= 4;

        #pragma unroll
        for (int l = 0; l < 3; l++) {
            #pragma unroll
            for (int q = 0; q < 4; q++) {
                const int pos = 3 - q, mask = 1 << pos;
                const int bit = (k >> pos) & 1;
                #pragma unroll
                for (int g = 0; g < 3; g++) {
                    const float2 cs = wcs[(l * 4 + q) * 3 + g];
                    const float c = cs.x, s = cs.y;
                    float nr, ni;
                    if (g == 2) {           // RZ (diagonal)
                        float t = bit ? -s : s;
                        nr = c * ar + t * ai;
                        ni = c * ai - t * ar;
                    } else {
                        float pr = __shfl_xor_sync(0xffffffffu, ar, mask);
                        float pi = __shfl_xor_sync(0xffffffffu, ai, mask);
                        if (g == 0) {       // RX
                            nr = c * ar + s * pi;
                            ni = c * ai - s * pr;
                        } else {            // RY
                            float t = bit ? s : -s;
                            nr = c * ar + t * pr;
                            ni = c * ai + t * pi;
                        }
                    }
                    ar = nr; ai = ni;
                }
            }
            ar = __shfl_sync(0xffffffffu, ar, sidx, 16);
            ai = __shfl_sync(0xffffffffu, ai, sidx, 16);
        }
        S[col][k] = make_float2(ar, ai);
    }
    __syncthreads();

    // ---------- A_q + collapse to 100 coefficients (shared atomics) ----------
    {
        const int i = tid >> 4, j = tid & 15;
        float s0 = 0.f, s1 = 0.f, s2 = 0.f, s3 = 0.f;
        #pragma unroll
        for (int k = 0; k < 16; k++) {
            float2 u = S[i][k], v = S[j][k];
            float p = u.x * v.x + u.y * v.y;
            s0 += ((k >> 3) & 1) ? -p : p;
            s1 += ((k >> 2) & 1) ? -p : p;
            s2 += ((k >> 1) & 1) ? -p : p;
            s3 += ( k       & 1) ? -p : p;
        }
        const int a_i = ((i >> 3) & 1) + ((i >> 1) & 1);
        const int b_i = ((i >> 2) & 1) + (i & 1);
        const int a_j = ((j >> 3) & 1) + ((j >> 1) & 1);
        const int b_j = ((j >> 2) & 1) + (j & 1);
        const int base = (a_i + a_j) * 5 + (b_i + b_j);
        atomicAdd(&coefS[base],      s0);
        atomicAdd(&coefS[25 + base], s1);
        atomicAdd(&coefS[50 + base], s2);
        atomicAdd(&coefS[75 + base], s3);
    }
    __syncthreads();
    if (tid < 100) { float v = coefS[tid]; scp[tid] = pk2(v, v); }
    __syncthreads();

    // ---------- batch phase: 2 pairs (4 samples) per thread ----------
    const int t0      = blockIdx.x * 256 + tid;
    const int tstride = gridDim.x * 256;

    u64 f0[PAIRS][5], f1[PAIRS][5];
    #pragma unroll
    for (int p = 0; p < PAIRS; p++) {
        const int pi_ = t0 + p * tstride;
        float4 xv = (pi_ < npair) ? x[pi_] : make_float4(0.f, 0.f, 0.f, 0.f);
        float c0a, s0a, c1a, s1a, c0b, s0b, c1b, s1b;
        __sincosf(0.5f * xv.x, &s0a, &c0a);
        __sincosf(0.5f * xv.y, &s1a, &c1a);
        __sincosf(0.5f * xv.z, &s0b, &c0b);
        __sincosf(0.5f * xv.w, &s1b, &c1b);
        const u64 c0 = pk2(c0a, c0b), s0 = pk2(s0a, s0b);
        const u64 c1 = pk2(c1a, c1b), s1 = pk2(s1a, s1b);
        const u64 c02 = mul2(c0, c0), s02 = mul2(s0, s0), cs0 = mul2(c0, s0);
        const u64 c12 = mul2(c1, c1), s12 = mul2(s1, s1), cs1 = mul2(c1, s1);
        f0[p][0] = mul2(c02, c02); f0[p][1] = mul2(c02, cs0); f0[p][2] = mul2(cs0, cs0);
        f0[p][3] = mul2(cs0, s02); f0[p][4] = mul2(s02, s02);
        f1[p][0] = mul2(c12, c12); f1[p][1] = mul2(c12, cs1); f1[p][2] = mul2(cs1, cs1);
        f1[p][3] = mul2(cs1, s12); f1[p][4] = mul2(s12, s12);
    }

    // accumulate all 4 outputs; coefficient loads shared across both pairs
    u64 accA[PAIRS][2], accB[PAIRS][2];   // q0,q1 in accA; q2,q3 in accB
    #pragma unroll
    for (int p = 0; p < PAIRS; p++) {
        accA[p][0] = accA[p][1] = accB[p][0] = accB[p][1] = 0ull;
    }
    #pragma unroll
    for (int qg = 0; qg < 2; qg++) {
        #pragma unroll
        for (int qq = 0; qq < 2; qq++) {
            const int q = qg * 2 + qq;
            #pragma unroll
            for (int a = 0; a < 5; a++) {
                const u64 r0 = scp[q * 25 + a * 5 + 0];
                const u64 r1 = scp[q * 25 + a * 5 + 1];
                const u64 r2 = scp[q * 25 + a * 5 + 2];
                const u64 r3 = scp[q * 25 + a * 5 + 3];
                const u64 r4 = scp[q * 25 + a * 5 + 4];
                #pragma unroll
                for (int p = 0; p < PAIRS; p++) {
                    u64 ts = mul2(r4, f1[p][4]);
                    ts = fma2(r3, f1[p][3], ts);
                    ts = fma2(r2, f1[p][2], ts);
                    ts = fma2(r1, f1[p][1], ts);
                    ts = fma2(r0, f1[p][0], ts);
                    if (qg == 0) accA[p][qq] = fma2(ts, f0[p][a], accA[p][qq]);
                    else         accB[p][qq] = fma2(ts, f0[p][a], accB[p][qq]);
                }
            }
        }
    }

    #pragma unroll
    for (int p = 0; p < PAIRS; p++) {
        const int pi_ = t0 + p * tstride;
        if (pi_ < npair) {
            float a0, b0, a1, b1, a2, b2, a3, b3;
            unpk2(accA[p][0], a0, b0);  // q0: sampleA, sampleB
            unpk2(accA[p][1], a1, b1);  // q1
            unpk2(accB[p][0], a2, b2);  // q2
            unpk2(accB[p][1], a3, b3);  // q3
            out[2 * pi_]     = make_float4(a0, a1, a2, a3);
            out[2 * pi_ + 1] = make_float4(b0, b1, b2, b3);
        }
    }
}

extern "C" void kernel_launch(void* const* d_in, const int* in_sizes, int n_in,
                              void* d_out, int out_size) {
    const float* x = (const float*)d_in[0];   // (B, 2)
    const float* w = (const float*)d_in[1];   // (3, 4, 3)
    const int n     = in_sizes[0] / 2;        // batch size (even)
    const int npair = n / 2;

    const int threads = (npair + PAIRS - 1) / PAIRS;
    const int blocks  = (threads + 255) / 256;
    qnn_fused<<<blocks, 256>>>((const float4*)x, (float4*)d_out, w, npair);
}

// round 5
// speedup vs baseline: 1.5008x; 1.5008x over previous
#include <cuda_runtime.h>
#include <cuda_bf16.h>

typedef unsigned long long u64;
__device__ __forceinline__ u64 pk2(float lo, float hi) {
    u64 r; asm("mov.b64 %0, {%1, %2};" : "=l"(r) : "f"(lo), "f"(hi)); return r;
}
__device__ __forceinline__ void unpk2(u64 v, float& lo, float& hi) {
    asm("mov.b64 {%0, %1}, %2;" : "=f"(lo), "=f"(hi) : "l"(v));
}
__device__ __forceinline__ u64 mul2(u64 a, u64 b) {
    u64 r; asm("mul.rn.f32x2 %0, %1, %2;" : "=l"(r) : "l"(a), "l"(b)); return r;
}
__device__ __forceinline__ u64 fma2(u64 a, u64 b, u64 c) {
    u64 r; asm("fma.rn.f32x2 %0, %1, %2, %3;" : "=l"(r) : "l"(a), "l"(b), "l"(c)); return r;
}

// Coefficients in trig basis v = (1, cos x, sin x, cos 2x, sin 2x),
// packed u64 (value duplicated in both f32 lanes), rows padded to 6 for
// 16B-aligned LDS.128 access: layout [q][alpha][6], 120 entries.
__device__ u64 g_coef_v[120];

// ---------------------------------------------------------------------------
// Setup kernel: ONE block, 256 threads. Shuffle-based 16x16 unitary sim
// (validated R3/R4), collapse to 100 monomial coefficients, then congruence
// transform into the trig basis and pack.
// ---------------------------------------------------------------------------
__global__ void __launch_bounds__(256) qnn_setup(const float* __restrict__ w) {
    __shared__ float2 wcs[36];
    __shared__ float2 S[16][16];
    __shared__ float  coefS[100];
    const int tid = threadIdx.x;

    if (tid < 36) {
        float s, c; __sincosf(0.5f * w[tid], &s, &c);
        wcs[tid] = make_float2(c, s);
    }
    if (tid >= 64 && tid < 164) coefS[tid - 64] = 0.f;
    __syncthreads();

    // simulate the 16x16 variational unitary: 16-lane group = one column
    {
        const int col = tid >> 4, k = tid & 15;
        float ar = (k == col) ? 1.f : 0.f, ai = 0.f;

        int sidx = k;                 // CNOT-ring inverse permutation
        if (sidx & 1) sidx ^= 8;
        if (sidx & 2) sidx ^= 1;
        if (sidx & 4) sidx ^= 2;
        if (sidx & 8) sidx ^= 4;

        #pragma unroll
        for (int l = 0; l < 3; l++) {
            #pragma unroll
            for (int q = 0; q < 4; q++) {
                const int pos = 3 - q, mask = 1 << pos;
                const int bit = (k >> pos) & 1;
                #pragma unroll
                for (int g = 0; g < 3; g++) {
                    const float2 cs = wcs[(l * 4 + q) * 3 + g];
                    const float c = cs.x, s = cs.y;
                    float nr, ni;
                    if (g == 2) {           // RZ
                        float t = bit ? -s : s;
                        nr = c * ar + t * ai;
                        ni = c * ai - t * ar;
                    } else {
                        float pr = __shfl_xor_sync(0xffffffffu, ar, mask);
                        float pi = __shfl_xor_sync(0xffffffffu, ai, mask);
                        if (g == 0) {       // RX
                            nr = c * ar + s * pi;
                            ni = c * ai - s * pr;
                        } else {            // RY
                            float t = bit ? s : -s;
                            nr = c * ar + t * pr;
                            ni = c * ai + t * pi;
                        }
                    }
                    ar = nr; ai = ni;
                }
            }
            ar = __shfl_sync(0xffffffffu, ar, sidx, 16);
            ai = __shfl_sync(0xffffffffu, ai, sidx, 16);
        }
        S[col][k] = make_float2(ar, ai);
    }
    __syncthreads();

    // A_q collapse to 100 monomial coefficients (shared atomics)
    {
        const int i = tid >> 4, j = tid & 15;
        float s0 = 0.f, s1 = 0.f, s2 = 0.f, s3 = 0.f;
        #pragma unroll
        for (int k = 0; k < 16; k++) {
            float2 u = S[i][k], v = S[j][k];
            float p = u.x * v.x + u.y * v.y;
            s0 += ((k >> 3) & 1) ? -p : p;
            s1 += ((k >> 2) & 1) ? -p : p;
            s2 += ((k >> 1) & 1) ? -p : p;
            s3 += ( k       & 1) ? -p : p;
        }
        const int a_i = ((i >> 3) & 1) + ((i >> 1) & 1);
        const int b_i = ((i >> 2) & 1) + (i & 1);
        const int a_j = ((j >> 3) & 1) + ((j >> 1) & 1);
        const int b_j = ((j >> 2) & 1) + (j & 1);
        const int base = (a_i + a_j) * 5 + (b_i + b_j);
        atomicAdd(&coefS[base],      s0);
        atomicAdd(&coefS[25 + base], s1);
        atomicAdd(&coefS[50 + base], s2);
        atomicAdd(&coefS[75 + base], s3);
    }
    __syncthreads();

    // congruence transform to trig basis: C_v = T^T C_f T, pack + pad
    // f[a] = sum_alpha T[a][alpha] * v[alpha];  all entries exact binary fracs
    if (tid < 120) {
        const float T[5][5] = {
            {0.375f,  0.5f, 0.f,   0.125f, 0.f    },
            {0.f,     0.f,  0.25f, 0.f,    0.125f },
            {0.125f,  0.f,  0.f,  -0.125f, 0.f    },
            {0.f,     0.f,  0.25f, 0.f,   -0.125f },
            {0.375f, -0.5f, 0.f,   0.125f, 0.f    }
        };
        const int q = tid / 30, r = tid % 30, al = r / 6, be = r % 6;
        float v = 0.f;
        if (be < 5) {
            for (int a = 0; a < 5; a++) {
                float ta = T[a][al];
                if (ta != 0.f) {
                    for (int b = 0; b < 5; b++) {
                        float tb = T[b][be];
                        if (tb != 0.f) v += ta * tb * coefS[q * 25 + a * 5 + b];
                    }
                }
            }
        }
        g_coef_v[tid] = pk2(v, v);
    }
}

// ---------------------------------------------------------------------------
// Batch kernel: 1 pair (2 samples) per thread, packed f32x2.
// v-basis: 2 full-angle sincos per sample, 4-FMA dots (v[0]=1, no mult).
// ---------------------------------------------------------------------------
__global__ void __launch_bounds__(256)
qnn_batch(const float4* __restrict__ x, float4* __restrict__ out, int npair) {
    __shared__ __align__(16) u64 scp[120];
    const int t = threadIdx.x;
    if (t < 120) scp[t] = g_coef_v[t];
    __syncthreads();

    const int idx = blockIdx.x * 256 + t;
    if (idx >= npair) return;

    const float4 xv = x[idx];   // (x0_A, x1_A, x0_B, x1_B)
    float c0a, s0a, c1a, s1a, c0b, s0b, c1b, s1b;
    __sincosf(xv.x, &s0a, &c0a);   // FULL angle
    __sincosf(xv.y, &s1a, &c1a);
    __sincosf(xv.z, &s0b, &c0b);
    __sincosf(xv.w, &s1b, &c1b);

    const u64 kTWO  = 0x4000000040000000ull;   // (2.0f, 2.0f)
    const u64 kNEG1 = 0xBF800000BF800000ull;   // (-1.0f, -1.0f)

    const u64 C0 = pk2(c0a, c0b), S0 = pk2(s0a, s0b);
    const u64 C1 = pk2(c1a, c1b), S1 = pk2(s1a, s1b);
    const u64 C20 = fma2(mul2(C0, C0), kTWO, kNEG1);   // cos 2x0
    const u64 S20 = mul2(mul2(C0, S0), kTWO);          // sin 2x0
    const u64 C21 = fma2(mul2(C1, C1), kTWO, kNEG1);
    const u64 S21 = mul2(mul2(C1, S1), kTWO);

    u64 v0[5]; v0[1] = C0; v0[2] = S0; v0[3] = C20; v0[4] = S20;

    u64 acc[4];
    #pragma unroll
    for (int q = 0; q < 4; q++) {
        u64 a_acc;
        #pragma unroll
        for (int al = 0; al < 5; al++) {
            const u64* row = &scp[q * 30 + al * 6];
            const ulonglong2 p01 = *(const ulonglong2*)(row);
            const ulonglong2 p23 = *(const ulonglong2*)(row + 2);
            const u64 r4 = row[4];
            u64 d = fma2(p01.y, C1, p01.x);   // r0 + r1*C1
            d = fma2(p23.x, S1, d);
            d = fma2(p23.y, C21, d);
            d = fma2(r4, S21, d);
            if (al == 0) a_acc = d;           // v0[0] = 1
            else         a_acc = fma2(d, v0[al], a_acc);
        }
        acc[q] = a_acc;
    }

    float a0, b0, a1, b1, a2, b2, a3, b3;
    unpk2(acc[0], a0, b0);
    unpk2(acc[1], a1, b1);
    unpk2(acc[2], a2, b2);
    unpk2(acc[3], a3, b3);
    out[2 * idx]     = make_float4(a0, a1, a2, a3);
    out[2 * idx + 1] = make_float4(b0, b1, b2, b3);
}

extern "C" void kernel_launch(void* const* d_in, const int* in_sizes, int n_in,
                              void* d_out, int out_size) {
    const float* x = (const float*)d_in[0];   // (B, 2)
    const float* w = (const float*)d_in[1];   // (3, 4, 3)
    const int n     = in_sizes[0] / 2;
    const int npair = n / 2;

    qnn_setup<<<1, 256>>>(w);
    const int blocks = (npair + 255) / 256;
    qnn_batch<<<blocks, 256>>>((const float4*)x, (float4*)d_out, npair);
}

// round 6
// speedup vs baseline: 1.6411x; 1.0935x over previous
#include <cuda_runtime.h>
#include <cuda_bf16.h>

typedef unsigned long long u64;
__device__ __forceinline__ u64 pk2(float lo, float hi) {
    u64 r; asm("mov.b64 %0, {%1, %2};" : "=l"(r) : "f"(lo), "f"(hi)); return r;
}
__device__ __forceinline__ void unpk2(u64 v, float& lo, float& hi) {
    asm("mov.b64 {%0, %1}, %2;" : "=f"(lo), "=f"(hi) : "l"(v));
}
__device__ __forceinline__ u64 mul2(u64 a, u64 b) {
    u64 r; asm("mul.rn.f32x2 %0, %1, %2;" : "=l"(r) : "l"(a), "l"(b)); return r;
}
__device__ __forceinline__ u64 fma2(u64 a, u64 b, u64 c) {
    u64 r; asm("fma.rn.f32x2 %0, %1, %2, %3;" : "=l"(r) : "l"(a), "l"(b), "l"(c)); return r;
}

// Coefficients in trig basis v = (1, cos x, sin x, cos 2x, sin 2x),
// packed u64 (both f32 lanes), rows padded to 6: layout [q][alpha][6].
__device__ u64 g_coef_v[120];

// ---------------------------------------------------------------------------
// Setup kernel (PDL primary): ONE block, 256 threads.
// ---------------------------------------------------------------------------
__global__ void __launch_bounds__(256) qnn_setup(const float* __restrict__ w) {
    __shared__ float2 wcs[36];
    __shared__ float2 S[16][16];
    __shared__ float  coefS[100];
    const int tid = threadIdx.x;

    if (tid < 36) {
        float s, c; __sincosf(0.5f * w[tid], &s, &c);
        wcs[tid] = make_float2(c, s);
    }
    if (tid >= 64 && tid < 164) coefS[tid - 64] = 0.f;
    __syncthreads();

    // simulate the 16x16 variational unitary: 16-lane group = one column
    {
        const int col = tid >> 4, k = tid & 15;
        float ar = (k == col) ? 1.f : 0.f, ai = 0.f;

        int sidx = k;                 // CNOT-ring inverse permutation
        if (sidx & 1) sidx ^= 8;
        if (sidx & 2) sidx ^= 1;
        if (sidx & 4) sidx ^= 2;
        if (sidx & 8) sidx ^= 4;

        #pragma unroll
        for (int l = 0; l < 3; l++) {
            #pragma unroll
            for (int q = 0; q < 4; q++) {
                const int pos = 3 - q, mask = 1 << pos;
                const int bit = (k >> pos) & 1;
                #pragma unroll
                for (int g = 0; g < 3; g++) {
                    const float2 cs = wcs[(l * 4 + q) * 3 + g];
                    const float c = cs.x, s = cs.y;
                    float nr, ni;
                    if (g == 2) {           // RZ
                        float t = bit ? -s : s;
                        nr = c * ar + t * ai;
                        ni = c * ai - t * ar;
                    } else {
                        float pr = __shfl_xor_sync(0xffffffffu, ar, mask);
                        float pi = __shfl_xor_sync(0xffffffffu, ai, mask);
                        if (g == 0) {       // RX
                            nr = c * ar + s * pi;
                            ni = c * ai - s * pr;
                        } else {            // RY
                            float t = bit ? s : -s;
                            nr = c * ar + t * pr;
                            ni = c * ai + t * pi;
                        }
                    }
                    ar = nr; ai = ni;
                }
            }
            ar = __shfl_sync(0xffffffffu, ar, sidx, 16);
            ai = __shfl_sync(0xffffffffu, ai, sidx, 16);
        }
        S[col][k] = make_float2(ar, ai);
    }
    __syncthreads();

    // A_q collapse to 100 monomial coefficients (shared atomics)
    {
        const int i = tid >> 4, j = tid & 15;
        float s0 = 0.f, s1 = 0.f, s2 = 0.f, s3 = 0.f;
        #pragma unroll
        for (int k = 0; k < 16; k++) {
            float2 u = S[i][k], v = S[j][k];
            float p = u.x * v.x + u.y * v.y;
            s0 += ((k >> 3) & 1) ? -p : p;
            s1 += ((k >> 2) & 1) ? -p : p;
            s2 += ((k >> 1) & 1) ? -p : p;
            s3 += ( k       & 1) ? -p : p;
        }
        const int a_i = ((i >> 3) & 1) + ((i >> 1) & 1);
        const int b_i = ((i >> 2) & 1) + (i & 1);
        const int a_j = ((j >> 3) & 1) + ((j >> 1) & 1);
        const int b_j = ((j >> 2) & 1) + (j & 1);
        const int base = (a_i + a_j) * 5 + (b_i + b_j);
        atomicAdd(&coefS[base],      s0);
        atomicAdd(&coefS[25 + base], s1);
        atomicAdd(&coefS[50 + base], s2);
        atomicAdd(&coefS[75 + base], s3);
    }
    __syncthreads();

    // congruence transform to trig basis: C_v = T^T C_f T (exact binary fracs)
    if (tid < 120) {
        const float T[5][5] = {
            {0.375f,  0.5f, 0.f,   0.125f, 0.f    },
            {0.f,     0.f,  0.25f, 0.f,    0.125f },
            {0.125f,  0.f,  0.f,  -0.125f, 0.f    },
            {0.f,     0.f,  0.25f, 0.f,   -0.125f },
            {0.375f, -0.5f, 0.f,   0.125f, 0.f    }
        };
        const int q = tid / 30, r = tid % 30, al = r / 6, be = r % 6;
        float v = 0.f;
        if (be < 5) {
            #pragma unroll
            for (int a = 0; a < 5; a++) {
                float ta = T[a][al];
                if (ta != 0.f) {
                    #pragma unroll
                    for (int b = 0; b < 5; b++) {
                        float tb = T[b][be];
                        if (tb != 0.f) v += ta * tb * coefS[q * 25 + a * 5 + b];
                    }
                }
            }
        }
        g_coef_v[tid] = pk2(v, v);
    }
    __threadfence();
    __syncthreads();
    if (tid == 0) cudaTriggerProgrammaticLaunchCompletion();
}

// ---------------------------------------------------------------------------
// Batch kernel (PDL secondary): 2 pairs (4 samples) per thread. Prelude
// overlaps the setup kernel; coefficients read after grid-dependency sync.
// ---------------------------------------------------------------------------
#define PAIRS 2

__global__ void __launch_bounds__(256)
qnn_batch(const float4* __restrict__ x, float4* __restrict__ out, int npair) {
    __shared__ __align__(16) u64 scp[120];
    const int tid = threadIdx.x;
    const int t0      = blockIdx.x * 256 + tid;
    const int tstride = gridDim.x * 256;

    const u64 kTWO  = 0x4000000040000000ull;   // (2.0f, 2.0f)
    const u64 kNEG1 = 0xBF800000BF800000ull;   // (-1.0f, -1.0f)

    // -------- prelude: independent of coefficients --------
    u64 C0[PAIRS], S0[PAIRS], C20[PAIRS], S20[PAIRS];
    u64 C1[PAIRS], S1[PAIRS], C21[PAIRS], S21[PAIRS];
    #pragma unroll
    for (int p = 0; p < PAIRS; p++) {
        const int pi_ = t0 + p * tstride;
        float4 xv = (pi_ < npair) ? x[pi_] : make_float4(0.f, 0.f, 0.f, 0.f);
        float c0a, s0a, c1a, s1a, c0b, s0b, c1b, s1b;
        __sincosf(xv.x, &s0a, &c0a);
        __sincosf(xv.y, &s1a, &c1a);
        __sincosf(xv.z, &s0b, &c0b);
        __sincosf(xv.w, &s1b, &c1b);
        C0[p] = pk2(c0a, c0b); S0[p] = pk2(s0a, s0b);
        C1[p] = pk2(c1a, c1b); S1[p] = pk2(s1a, s1b);
        C20[p] = fma2(mul2(C0[p], C0[p]), kTWO, kNEG1);
        S20[p] = mul2(mul2(C0[p], S0[p]), kTWO);
        C21[p] = fma2(mul2(C1[p], C1[p]), kTWO, kNEG1);
        S21[p] = mul2(mul2(C1[p], S1[p]), kTWO);
    }

    // -------- wait for setup's coefficients, stage to shared --------
    cudaGridDependencySynchronize();
    if (tid < 120) scp[tid] = g_coef_v[tid];
    __syncthreads();

    // -------- bilinear forms: coefficient loads shared across both pairs --------
    u64 o0[PAIRS], o1[PAIRS], o2[PAIRS], o3[PAIRS];
    #pragma unroll
    for (int q = 0; q < 4; q++) {
        #pragma unroll
        for (int al = 0; al < 5; al++) {
            const u64* row = &scp[q * 30 + al * 6];
            const ulonglong2 p01 = *(const ulonglong2*)(row);
            const ulonglong2 p23 = *(const ulonglong2*)(row + 2);
            const u64 r4 = row[4];
            #pragma unroll
            for (int p = 0; p < PAIRS; p++) {
                u64 d = fma2(p01.y, C1[p], p01.x);
                d = fma2(p23.x, S1[p], d);
                d = fma2(p23.y, C21[p], d);
                d = fma2(r4,    S21[p], d);
                u64* dst = (q == 0) ? o0 : (q == 1) ? o1 : (q == 2) ? o2 : o3;
                if (al == 0)      dst[p] = d;                       // v0[0] = 1
                else if (al == 1) dst[p] = fma2(d, C0[p],  dst[p]);
                else if (al == 2) dst[p] = fma2(d, S0[p],  dst[p]);
                else if (al == 3) dst[p] = fma2(d, C20[p], dst[p]);
                else              dst[p] = fma2(d, S20[p], dst[p]);
            }
        }
    }

    #pragma unroll
    for (int p = 0; p < PAIRS; p++) {
        const int pi_ = t0 + p * tstride;
        if (pi_ < npair) {
            float a0, b0, a1, b1, a2, b2, a3, b3;
            unpk2(o0[p], a0, b0);
            unpk2(o1[p], a1, b1);
            unpk2(o2[p], a2, b2);
            unpk2(o3[p], a3, b3);
            out[2 * pi_]     = make_float4(a0, a1, a2, a3);
            out[2 * pi_ + 1] = make_float4(b0, b1, b2, b3);
        }
    }
}

extern "C" void kernel_launch(void* const* d_in, const int* in_sizes, int n_in,
                              void* d_out, int out_size) {
    const float* x = (const float*)d_in[0];   // (B, 2)
    const float* w = (const float*)d_in[1];   // (3, 4, 3)
    const int n     = in_sizes[0] / 2;
    const int npair = n / 2;

    qnn_setup<<<1, 256>>>(w);

    const int threads = (npair + PAIRS - 1) / PAIRS;
    const int blocks  = (threads + 255) / 256;

    cudaLaunchConfig_t cfg = {};
    cfg.gridDim  = dim3((unsigned)blocks, 1, 1);
    cfg.blockDim = dim3(256, 1, 1);
    cfg.dynamicSmemBytes = 0;
    cfg.stream = 0;
    cudaLaunchAttribute attrs[1];
    attrs[0].id = cudaLaunchAttributeProgrammaticStreamSerialization;
    attrs[0].val.programmaticStreamSerializationAllowed = 1;
    cfg.attrs = attrs;
    cfg.numAttrs = 1;
    cudaLaunchKernelEx(&cfg, qnn_batch, (const float4*)x, (float4*)d_out, npair);
}

// round 7
// speedup vs baseline: 1.9899x; 1.2126x over previous
#include <cuda_runtime.h>
#include <cuda_bf16.h>

typedef unsigned long long u64;
__device__ __forceinline__ u64 pk2(float lo, float hi) {
    u64 r; asm("mov.b64 %0, {%1, %2};" : "=l"(r) : "f"(lo), "f"(hi)); return r;
}
__device__ __forceinline__ void unpk2(u64 v, float& lo, float& hi) {
    asm("mov.b64 {%0, %1}, %2;" : "=f"(lo), "=f"(hi) : "l"(v));
}
__device__ __forceinline__ u64 mul2(u64 a, u64 b) {
    u64 r; asm("mul.rn.f32x2 %0, %1, %2;" : "=l"(r) : "l"(a), "l"(b)); return r;
}
__device__ __forceinline__ u64 fma2(u64 a, u64 b, u64 c) {
    u64 r; asm("fma.rn.f32x2 %0, %1, %2, %3;" : "=l"(r) : "l"(a), "l"(b), "l"(c)); return r;
}

// Coefficients in trig basis v = (1, cos x, sin x, cos 2x, sin 2x),
// packed u64 (both f32 lanes), rows padded to 6: layout [q][alpha][6].
__device__ u64 g_coef_v[120];
__device__ int g_flag = 0;

#define PAIRS 2

// ---------------------------------------------------------------------------
// Single kernel. Block 0: shuffle-based 16x16 unitary sim -> 100 monomial
// coefs -> congruence transform to trig basis -> publish + release flag.
// All blocks: coefficient-independent prelude, acquire flag, bilinear forms.
// ---------------------------------------------------------------------------
__global__ void __launch_bounds__(256)
qnn_all(const float4* __restrict__ x, float4* __restrict__ out,
        const float* __restrict__ w, int npair)
{
    __shared__ __align__(16) u64 scp[120];
    const int tid = threadIdx.x;

    // ================= block 0: setup =================
    if (blockIdx.x == 0) {
        __shared__ float2 wcs[36];
        __shared__ float2 S[16][16];
        __shared__ float  coefS[100];

        if (tid < 36) {
            float s, c; __sincosf(0.5f * w[tid], &s, &c);
            wcs[tid] = make_float2(c, s);
        }
        if (tid >= 64 && tid < 164) coefS[tid - 64] = 0.f;
        __syncthreads();

        // 16-lane group = one column of the 16x16 unitary
        {
            const int col = tid >> 4, k = tid & 15;
            float ar = (k == col) ? 1.f : 0.f, ai = 0.f;

            int sidx = k;                 // CNOT-ring inverse permutation
            if (sidx & 1) sidx ^= 8;
            if (sidx & 2) sidx ^= 1;
            if (sidx & 4) sidx ^= 2;
            if (sidx & 8) sidx ^= 4;

            #pragma unroll
            for (int l = 0; l < 3; l++) {
                #pragma unroll
                for (int q = 0; q < 4; q++) {
                    const int pos = 3 - q, mask = 1 << pos;
                    const int bit = (k >> pos) & 1;
                    #pragma unroll
                    for (int g = 0; g < 3; g++) {
                        const float2 cs = wcs[(l * 4 + q) * 3 + g];
                        const float c = cs.x, s = cs.y;
                        float nr, ni;
                        if (g == 2) {           // RZ
                            float t = bit ? -s : s;
                            nr = c * ar + t * ai;
                            ni = c * ai - t * ar;
                        } else {
                            float pr = __shfl_xor_sync(0xffffffffu, ar, mask);
                            float pi = __shfl_xor_sync(0xffffffffu, ai, mask);
                            if (g == 0) {       // RX
                                nr = c * ar + s * pi;
                                ni = c * ai - s * pr;
                            } else {            // RY
                                float t = bit ? s : -s;
                                nr = c * ar + t * pr;
                                ni = c * ai + t * pi;
                            }
                        }
                        ar = nr; ai = ni;
                    }
                }
                ar = __shfl_sync(0xffffffffu, ar, sidx, 16);
                ai = __shfl_sync(0xffffffffu, ai, sidx, 16);
            }
            S[col][k] = make_float2(ar, ai);
        }
        __syncthreads();

        // A_q collapse -> 100 monomial coefficients (shared atomics)
        {
            const int i = tid >> 4, j = tid & 15;
            float s0 = 0.f, s1 = 0.f, s2 = 0.f, s3 = 0.f;
            #pragma unroll
            for (int k = 0; k < 16; k++) {
                float2 u = S[i][k], v = S[j][k];
                float p = u.x * v.x + u.y * v.y;
                s0 += ((k >> 3) & 1) ? -p : p;
                s1 += ((k >> 2) & 1) ? -p : p;
                s2 += ((k >> 1) & 1) ? -p : p;
                s3 += ( k       & 1) ? -p : p;
            }
            const int a_i = ((i >> 3) & 1) + ((i >> 1) & 1);
            const int b_i = ((i >> 2) & 1) + (i & 1);
            const int a_j = ((j >> 3) & 1) + ((j >> 1) & 1);
            const int b_j = ((j >> 2) & 1) + (j & 1);
            const int base = (a_i + a_j) * 5 + (b_i + b_j);
            atomicAdd(&coefS[base],      s0);
            atomicAdd(&coefS[25 + base], s1);
            atomicAdd(&coefS[50 + base], s2);
            atomicAdd(&coefS[75 + base], s3);
        }
        __syncthreads();

        // congruence transform to trig basis: C_v = T^T C_f T (exact fracs)
        if (tid < 120) {
            const float T[5][5] = {
                {0.375f,  0.5f, 0.f,   0.125f, 0.f    },
                {0.f,     0.f,  0.25f, 0.f,    0.125f },
                {0.125f,  0.f,  0.f,  -0.125f, 0.f    },
                {0.f,     0.f,  0.25f, 0.f,   -0.125f },
                {0.375f, -0.5f, 0.f,   0.125f, 0.f    }
            };
            const int q = tid / 30, r = tid % 30, al = r / 6, be = r % 6;
            float v = 0.f;
            if (be < 5) {
                #pragma unroll
                for (int a = 0; a < 5; a++) {
                    float ta = T[a][al];
                    if (ta != 0.f) {
                        #pragma unroll
                        for (int b = 0; b < 5; b++) {
                            float tb = T[b][be];
                            if (tb != 0.f) v += ta * tb * coefS[q * 25 + a * 5 + b];
                        }
                    }
                }
            }
            u64 pv = pk2(v, v);
            g_coef_v[tid] = pv;
            scp[tid] = pv;                 // block 0 stages locally
        }
        __threadfence();
        __syncthreads();
        if (tid == 0) {
            asm volatile("st.release.gpu.global.b32 [%0], %1;"
                         :: "l"(&g_flag), "r"(1) : "memory");
        }
        __syncthreads();
    }

    // ================= all blocks: batch =================
    const int t0      = blockIdx.x * 256 + tid;
    const int tstride = gridDim.x * 256;

    const u64 kTWO  = 0x4000000040000000ull;   // (2.0f, 2.0f)
    const u64 kNEG1 = 0xBF800000BF800000ull;   // (-1.0f, -1.0f)

    // -------- prelude: independent of coefficients --------
    u64 C0[PAIRS], S0[PAIRS], C20[PAIRS], S20[PAIRS];
    u64 C1[PAIRS], S1[PAIRS], C21[PAIRS], S21[PAIRS];
    #pragma unroll
    for (int p = 0; p < PAIRS; p++) {
        const int pi_ = t0 + p * tstride;
        float4 xv = (pi_ < npair) ? x[pi_] : make_float4(0.f, 0.f, 0.f, 0.f);
        float c0a, s0a, c1a, s1a, c0b, s0b, c1b, s1b;
        __sincosf(xv.x, &s0a, &c0a);
        __sincosf(xv.y, &s1a, &c1a);
        __sincosf(xv.z, &s0b, &c0b);
        __sincosf(xv.w, &s1b, &c1b);
        C0[p] = pk2(c0a, c0b); S0[p] = pk2(s0a, s0b);
        C1[p] = pk2(c1a, c1b); S1[p] = pk2(s1a, s1b);
        C20[p] = fma2(mul2(C0[p], C0[p]), kTWO, kNEG1);
        S20[p] = mul2(mul2(C0[p], S0[p]), kTWO);
        C21[p] = fma2(mul2(C1[p], C1[p]), kTWO, kNEG1);
        S21[p] = mul2(mul2(C1[p], S1[p]), kTWO);
    }

    // -------- acquire coefficients --------
    if (blockIdx.x != 0) {
        if (tid == 0) {
            int f;
            do {
                asm volatile("ld.acquire.gpu.global.b32 %0, [%1];"
                             : "=r"(f) : "l"(&g_flag) : "memory");
                if (!f) __nanosleep(64);
            } while (!f);
        }
        __syncthreads();
        if (tid < 120) scp[tid] = g_coef_v[tid];
        __syncthreads();
    }

    // -------- bilinear forms: coefficient loads shared across both pairs ----
    u64 o0[PAIRS], o1[PAIRS], o2[PAIRS], o3[PAIRS];
    #pragma unroll
    for (int q = 0; q < 4; q++) {
        #pragma unroll
        for (int al = 0; al < 5; al++) {
            const u64* row = &scp[q * 30 + al * 6];
            const ulonglong2 p01 = *(const ulonglong2*)(row);
            const ulonglong2 p23 = *(const ulonglong2*)(row + 2);
            const u64 r4 = row[4];
            #pragma unroll
            for (int p = 0; p < PAIRS; p++) {
                u64 d = fma2(p01.y, C1[p], p01.x);
                d = fma2(p23.x, S1[p], d);
                d = fma2(p23.y, C21[p], d);
                d = fma2(r4,    S21[p], d);
                u64* dst = (q == 0) ? o0 : (q == 1) ? o1 : (q == 2) ? o2 : o3;
                if (al == 0)      dst[p] = d;                       // v[0] = 1
                else if (al == 1) dst[p] = fma2(d, C0[p],  dst[p]);
                else if (al == 2) dst[p] = fma2(d, S0[p],  dst[p]);
                else if (al == 3) dst[p] = fma2(d, C20[p], dst[p]);
                else              dst[p] = fma2(d, S20[p], dst[p]);
            }
        }
    }

    #pragma unroll
    for (int p = 0; p < PAIRS; p++) {
        const int pi_ = t0 + p * tstride;
        if (pi_ < npair) {
            float a0, b0, a1, b1, a2, b2, a3, b3;
            unpk2(o0[p], a0, b0);
            unpk2(o1[p], a1, b1);
            unpk2(o2[p], a2, b2);
            unpk2(o3[p], a3, b3);
            out[2 * pi_]     = make_float4(a0, a1, a2, a3);
            out[2 * pi_ + 1] = make_float4(b0, b1, b2, b3);
        }
    }
}

extern "C" void kernel_launch(void* const* d_in, const int* in_sizes, int n_in,
                              void* d_out, int out_size) {
    const float* x = (const float*)d_in[0];   // (B, 2)
    const float* w = (const float*)d_in[1];   // (3, 4, 3)
    const int n     = in_sizes[0] / 2;
    const int npair = n / 2;

    const int threads = (npair + PAIRS - 1) / PAIRS;
    const int blocks  = (threads + 255) / 256;
    qnn_all<<<blocks, 256>>>((const float4*)x, (float4*)d_out, w, npair);
}

// round 8
// speedup vs baseline: 2.4093x; 1.2108x over previous
#include <cuda_runtime.h>
#include <cuda_bf16.h>

typedef unsigned long long u64;
__device__ __forceinline__ u64 pk2(float lo, float hi) {
    u64 r; asm("mov.b64 %0, {%1, %2};" : "=l"(r) : "f"(lo), "f"(hi)); return r;
}
__device__ __forceinline__ void unpk2(u64 v, float& lo, float& hi) {
    asm("mov.b64 {%0, %1}, %2;" : "=f"(lo), "=f"(hi) : "l"(v));
}
__device__ __forceinline__ u64 mul2(u64 a, u64 b) {
    u64 r; asm("mul.rn.f32x2 %0, %1, %2;" : "=l"(r) : "l"(a), "l"(b)); return r;
}
__device__ __forceinline__ u64 fma2(u64 a, u64 b, u64 c) {
    u64 r; asm("fma.rn.f32x2 %0, %1, %2, %3;" : "=l"(r) : "l"(a), "l"(b), "l"(c)); return r;
}

// Coefficients in trig basis v = (1, cos x, sin x, cos 2x, sin 2x),
// packed u64 (both f32 lanes), rows padded to 6: layout [q][alpha][6].
__device__ u64 g_coef_v[120];
__device__ int g_flag = 0;

#define PAIRS 2

// ---------------------------------------------------------------------------
// Setup path (block 0 only), isolated via noinline so the batch path gets
// clean straight-line regalloc/scheduling.
// ---------------------------------------------------------------------------
__device__ __noinline__ void do_setup(const float* __restrict__ w, int tid) {
    __shared__ float2 wcs[36];
    __shared__ float2 S[16][16];
    __shared__ float  coefS[100];

    if (tid < 36) {
        float s, c; __sincosf(0.5f * w[tid], &s, &c);
        wcs[tid] = make_float2(c, s);
    }
    if (tid >= 64 && tid < 164) coefS[tid - 64] = 0.f;
    __syncthreads();

    // 16-lane group = one column of the 16x16 unitary
    {
        const int col = tid >> 4, k = tid & 15;
        float ar = (k == col) ? 1.f : 0.f, ai = 0.f;

        int sidx = k;                 // CNOT-ring inverse permutation
        if (sidx & 1) sidx ^= 8;
        if (sidx & 2) sidx ^= 1;
        if (sidx & 4) sidx ^= 2;
        if (sidx & 8) sidx ^= 4;

        #pragma unroll
        for (int l = 0; l < 3; l++) {
            #pragma unroll
            for (int q = 0; q < 4; q++) {
                const int pos = 3 - q, mask = 1 << pos;
                const int bit = (k >> pos) & 1;
                #pragma unroll
                for (int g = 0; g < 3; g++) {
                    const float2 cs = wcs[(l * 4 + q) * 3 + g];
                    const float c = cs.x, s = cs.y;
                    float nr, ni;
                    if (g == 2) {           // RZ
                        float t = bit ? -s : s;
                        nr = c * ar + t * ai;
                        ni = c * ai - t * ar;
                    } else {
                        float pr = __shfl_xor_sync(0xffffffffu, ar, mask);
                        float pi = __shfl_xor_sync(0xffffffffu, ai, mask);
                        if (g == 0) {       // RX
                            nr = c * ar + s * pi;
                            ni = c * ai - s * pr;
                        } else {            // RY
                            float t = bit ? s : -s;
                            nr = c * ar + t * pr;
                            ni = c * ai + t * pi;
                        }
                    }
                    ar = nr; ai = ni;
                }
            }
            ar = __shfl_sync(0xffffffffu, ar, sidx, 16);
            ai = __shfl_sync(0xffffffffu, ai, sidx, 16);
        }
        S[col][k] = make_float2(ar, ai);
    }
    __syncthreads();

    // A_q collapse -> 100 monomial coefficients (shared atomics)
    {
        const int i = tid >> 4, j = tid & 15;
        float s0 = 0.f, s1 = 0.f, s2 = 0.f, s3 = 0.f;
        #pragma unroll
        for (int k = 0; k < 16; k++) {
            float2 u = S[i][k], v = S[j][k];
            float p = u.x * v.x + u.y * v.y;
            s0 += ((k >> 3) & 1) ? -p : p;
            s1 += ((k >> 2) & 1) ? -p : p;
            s2 += ((k >> 1) & 1) ? -p : p;
            s3 += ( k       & 1) ? -p : p;
        }
        const int a_i = ((i >> 3) & 1) + ((i >> 1) & 1);
        const int b_i = ((i >> 2) & 1) + (i & 1);
        const int a_j = ((j >> 3) & 1) + ((j >> 1) & 1);
        const int b_j = ((j >> 2) & 1) + (j & 1);
        const int base = (a_i + a_j) * 5 + (b_i + b_j);
        atomicAdd(&coefS[base],      s0);
        atomicAdd(&coefS[25 + base], s1);
        atomicAdd(&coefS[50 + base], s2);
        atomicAdd(&coefS[75 + base], s3);
    }
    __syncthreads();

    // congruence transform to trig basis: C_v = T^T C_f T (exact fracs)
    if (tid < 120) {
        const float T[5][5] = {
            {0.375f,  0.5f, 0.f,   0.125f, 0.f    },
            {0.f,     0.f,  0.25f, 0.f,    0.125f },
            {0.125f,  0.f,  0.f,  -0.125f, 0.f    },
            {0.f,     0.f,  0.25f, 0.f,   -0.125f },
            {0.375f, -0.5f, 0.f,   0.125f, 0.f    }
        };
        const int q = tid / 30, r = tid % 30, al = r / 6, be = r % 6;
        float v = 0.f;
        if (be < 5) {
            #pragma unroll
            for (int a = 0; a < 5; a++) {
                float ta = T[a][al];
                if (ta != 0.f) {
                    #pragma unroll
                    for (int b = 0; b < 5; b++) {
                        float tb = T[b][be];
                        if (tb != 0.f) v += ta * tb * coefS[q * 25 + a * 5 + b];
                    }
                }
            }
        }
        g_coef_v[tid] = pk2(v, v);
    }
    __threadfence();
    __syncthreads();
    if (tid == 0) {
        asm volatile("st.release.gpu.global.b32 [%0], %1;"
                     :: "l"(&g_flag), "r"(1) : "memory");
    }
}

// ---------------------------------------------------------------------------
// Single kernel. Block 0 = setup-only, then exits. Blocks 1..N = batch.
// ---------------------------------------------------------------------------
__global__ void __launch_bounds__(256, 4)
qnn_all(const float4* __restrict__ x, float4* __restrict__ out,
        const float* __restrict__ w, int npair)
{
    __shared__ __align__(16) u64 scp[120];
    const int tid = threadIdx.x;

    if (blockIdx.x == 0) {
        do_setup(w, tid);
        return;
    }

    const int t0      = (blockIdx.x - 1) * 256 + tid;
    const int tstride = (gridDim.x - 1) * 256;

    const u64 kTWO  = 0x4000000040000000ull;   // (2.0f, 2.0f)
    const u64 kNEG1 = 0xBF800000BF800000ull;   // (-1.0f, -1.0f)

    // -------- prelude: independent of coefficients --------
    u64 C0[PAIRS], S0[PAIRS], C20[PAIRS], S20[PAIRS];
    u64 C1[PAIRS], S1[PAIRS], C21[PAIRS], S21[PAIRS];
    #pragma unroll
    for (int p = 0; p < PAIRS; p++) {
        const int pi_ = t0 + p * tstride;
        float4 xv = (pi_ < npair) ? x[pi_] : make_float4(0.f, 0.f, 0.f, 0.f);
        float c0a, s0a, c1a, s1a, c0b, s0b, c1b, s1b;
        __sincosf(xv.x, &s0a, &c0a);
        __sincosf(xv.y, &s1a, &c1a);
        __sincosf(xv.z, &s0b, &c0b);
        __sincosf(xv.w, &s1b, &c1b);
        C0[p] = pk2(c0a, c0b); S0[p] = pk2(s0a, s0b);
        C1[p] = pk2(c1a, c1b); S1[p] = pk2(s1a, s1b);
        C20[p] = fma2(mul2(C0[p], C0[p]), kTWO, kNEG1);
        S20[p] = mul2(mul2(C0[p], S0[p]), kTWO);
        C21[p] = fma2(mul2(C1[p], C1[p]), kTWO, kNEG1);
        S21[p] = mul2(mul2(C1[p], S1[p]), kTWO);
    }

    // -------- acquire coefficients (fast path: flag already set) --------
    if (tid == 0) {
        int f;
        asm volatile("ld.acquire.gpu.global.b32 %0, [%1];"
                     : "=r"(f) : "l"(&g_flag) : "memory");
        while (!f) {
            __nanosleep(256);
            asm volatile("ld.acquire.gpu.global.b32 %0, [%1];"
                         : "=r"(f) : "l"(&g_flag) : "memory");
        }
    }
    __syncthreads();
    if (tid < 120) scp[tid] = g_coef_v[tid];
    __syncthreads();

    // -------- bilinear forms: coefficient loads shared across both pairs ----
    u64 o0[PAIRS], o1[PAIRS], o2[PAIRS], o3[PAIRS];
    #pragma unroll
    for (int q = 0; q < 4; q++) {
        #pragma unroll
        for (int al = 0; al < 5; al++) {
            const u64* row = &scp[q * 30 + al * 6];
            const ulonglong2 p01 = *(const ulonglong2*)(row);
            const ulonglong2 p23 = *(const ulonglong2*)(row + 2);
            const u64 r4 = row[4];
            #pragma unroll
            for (int p = 0; p < PAIRS; p++) {
                u64 d = fma2(p01.y, C1[p], p01.x);
                d = fma2(p23.x, S1[p], d);
                d = fma2(p23.y, C21[p], d);
                d = fma2(r4,    S21[p], d);
                u64* dst = (q == 0) ? o0 : (q == 1) ? o1 : (q == 2) ? o2 : o3;
                if (al == 0)      dst[p] = d;                       // v[0] = 1
                else if (al == 1) dst[p] = fma2(d, C0[p],  dst[p]);
                else if (al == 2) dst[p] = fma2(d, S0[p],  dst[p]);
                else if (al == 3) dst[p] = fma2(d, C20[p], dst[p]);
                else              dst[p] = fma2(d, S20[p], dst[p]);
            }
        }
    }

    #pragma unroll
    for (int p = 0; p < PAIRS; p++) {
        const int pi_ = t0 + p * tstride;
        if (pi_ < npair) {
            float a0, b0, a1, b1, a2, b2, a3, b3;
            unpk2(o0[p], a0, b0);
            unpk2(o1[p], a1, b1);
            unpk2(o2[p], a2, b2);
            unpk2(o3[p], a3, b3);
            out[2 * pi_]     = make_float4(a0, a1, a2, a3);
            out[2 * pi_ + 1] = make_float4(b0, b1, b2, b3);
        }
    }
}

extern "C" void kernel_launch(void* const* d_in, const int* in_sizes, int n_in,
                              void* d_out, int out_size) {
    const float* x = (const float*)d_in[0];   // (B, 2)
    const float* w = (const float*)d_in[1];   // (3, 4, 3)
    const int n     = in_sizes[0] / 2;
    const int npair = n / 2;

    const int threads = (npair + PAIRS - 1) / PAIRS;
    const int blocks  = (threads + 255) / 256 + 1;   // +1 setup block
    qnn_all<<<blocks, 256>>>((const float4*)x, (float4*)d_out, w, npair);
}